// round 11
// baseline (speedup 1.0000x reference)
#include <cuda_runtime.h>
#include <cuda_bf16.h>
#include <cstdint>

// ---------------------------------------------------------------------------
// RelPosQTransformerLayer — R9: tensor-core flash attention + mma GEMMs
//   B=2, Q=512, A=4096, D=512, H=8, DK=64, DFF=2048, MD=100
// ---------------------------------------------------------------------------

namespace cfg {
constexpr int B = 2, Q = 512, A = 4096, D = 512, H = 8, DK = 64, DFF = 2048, MD = 100;
constexpr float NEG = -1e9f;
}
using namespace cfg;

// ---------------- device scratch (allocation-free) ----------------
__device__ float g_q[B * Q * D];
__device__ float g_k[B * A * D];
__device__ float g_v[B * A * D];
__device__ float g_res1[B * Q * D];
__device__ float g_x1[B * Q * D];
__device__ float g_res2[B * Q * D];
__device__ int g_mask_is_byte;

// attention split-A partials (unnormalized)
__device__ float g_po[2][B * H * Q * DK];
__device__ float g_pm[2][B * H * Q];
__device__ float g_pl[2][B * H * Q];

// bf16 hi/lo split buffers
__device__ __nv_bfloat16 b_qt_h[B * Q * D], b_qt_l[B * Q * D];
__device__ __nv_bfloat16 b_at_h[B * A * D], b_at_l[B * A * D];
__device__ __nv_bfloat16 b_ctx_h[B * Q * D], b_ctx_l[B * Q * D];
__device__ __nv_bfloat16 b_x1_h[B * Q * D], b_x1_l[B * Q * D];
__device__ __nv_bfloat16 b_ff1_h[B * Q * DFF], b_ff1_l[B * Q * DFF];
__device__ __nv_bfloat16 b_wq_h[D * D], b_wq_l[D * D];
__device__ __nv_bfloat16 b_wk_h[D * D], b_wk_l[D * D];
__device__ __nv_bfloat16 b_wv_h[D * D], b_wv_l[D * D];
__device__ __nv_bfloat16 b_wo_h[D * D], b_wo_l[D * D];
__device__ __nv_bfloat16 b_w1_h[DFF * D], b_w1_l[DFF * D];
__device__ __nv_bfloat16 b_w2_h[D * DFF], b_w2_l[D * DFF];

// ---------------- small helpers ----------------
__global__ void detect_mask_kernel(const unsigned int* __restrict__ fm) {
    g_mask_is_byte = (*fm == 0x01010101u) ? 1 : 0;
}
__device__ __forceinline__ bool mask_at(const void* p, size_t i, int is_byte) {
    if (is_byte) return ((const unsigned char*)p)[i] != 0;
    return ((const unsigned int*)p)[i] != 0u;
}
__device__ __forceinline__ uint32_t pack_bf(float a, float b) {
    __nv_bfloat162 t = __float22bfloat162_rn(make_float2(a, b));
    return *reinterpret_cast<uint32_t*>(&t);
}

__global__ void __launch_bounds__(256) split_kernel(
    const float* __restrict__ x, __nv_bfloat16* __restrict__ hi,
    __nv_bfloat16* __restrict__ lo, int n4)
{
    for (int i = blockIdx.x * blockDim.x + threadIdx.x; i < n4;
         i += gridDim.x * blockDim.x) {
        float4 v = reinterpret_cast<const float4*>(x)[i];
        __nv_bfloat16 h0 = __float2bfloat16(v.x);
        __nv_bfloat16 h1 = __float2bfloat16(v.y);
        __nv_bfloat16 h2 = __float2bfloat16(v.z);
        __nv_bfloat16 h3 = __float2bfloat16(v.w);
        __nv_bfloat16 l0 = __float2bfloat16(v.x - __bfloat162float(h0));
        __nv_bfloat16 l1 = __float2bfloat16(v.y - __bfloat162float(h1));
        __nv_bfloat16 l2 = __float2bfloat16(v.z - __bfloat162float(h2));
        __nv_bfloat16 l3 = __float2bfloat16(v.w - __bfloat162float(h3));
        reinterpret_cast<__nv_bfloat162*>(hi)[i * 2 + 0] = __nv_bfloat162(h0, h1);
        reinterpret_cast<__nv_bfloat162*>(hi)[i * 2 + 1] = __nv_bfloat162(h2, h3);
        reinterpret_cast<__nv_bfloat162*>(lo)[i * 2 + 0] = __nv_bfloat162(l0, l1);
        reinterpret_cast<__nv_bfloat162*>(lo)[i * 2 + 1] = __nv_bfloat162(l2, l3);
    }
}

// ---------------- mma.sync / ldmatrix / cp.async wrappers ----------------
__device__ __forceinline__ uint32_t smem_u32(const void* p) {
    return (uint32_t)__cvta_generic_to_shared(p);
}
__device__ __forceinline__ void ldsm4(uint32_t r[4], uint32_t addr) {
    asm volatile(
        "ldmatrix.sync.aligned.m8n8.x4.shared.b16 {%0,%1,%2,%3}, [%4];"
        : "=r"(r[0]), "=r"(r[1]), "=r"(r[2]), "=r"(r[3])
        : "r"(addr));
}
__device__ __forceinline__ void ldsm4t(uint32_t r[4], uint32_t addr) {
    asm volatile(
        "ldmatrix.sync.aligned.m8n8.x4.trans.shared.b16 {%0,%1,%2,%3}, [%4];"
        : "=r"(r[0]), "=r"(r[1]), "=r"(r[2]), "=r"(r[3])
        : "r"(addr));
}
__device__ __forceinline__ void mma16816(float c[4], const uint32_t a[4],
                                         uint32_t b0, uint32_t b1) {
    asm volatile(
        "mma.sync.aligned.m16n8k16.row.col.f32.bf16.bf16.f32 "
        "{%0,%1,%2,%3}, {%4,%5,%6,%7}, {%8,%9}, {%0,%1,%2,%3};"
        : "+f"(c[0]), "+f"(c[1]), "+f"(c[2]), "+f"(c[3])
        : "r"(a[0]), "r"(a[1]), "r"(a[2]), "r"(a[3]), "r"(b0), "r"(b1));
}
__device__ __forceinline__ void cp16(uint32_t saddr, const void* g) {
    asm volatile("cp.async.cg.shared.global [%0], [%1], 16;"
                 :: "r"(saddr), "l"(g) : "memory");
}
#define CP_COMMIT() asm volatile("cp.async.commit_group;" ::: "memory")
#define CP_WAIT(n) asm volatile("cp.async.wait_group %0;" :: "n"(n) : "memory")

// ---------------------------------------------------------------------------
// mma.sync split-bf16 GEMM (from R4, validated). OSPLIT: write bf16 hi/lo.
// ---------------------------------------------------------------------------
template <bool RELU, bool RES, bool OSPLIT>
__global__ void __launch_bounds__(256, 2) gemm_mma(
    const __nv_bfloat16* __restrict__ Ah, const __nv_bfloat16* __restrict__ Al,
    const __nv_bfloat16* __restrict__ Wh, const __nv_bfloat16* __restrict__ Wl,
    const float* __restrict__ bias, const float* __restrict__ res,
    float* __restrict__ C, __nv_bfloat16* __restrict__ Ch,
    __nv_bfloat16* __restrict__ Cl, int M, int N, int K)
{
    extern __shared__ char dsm[];
    const uint32_t sbase = smem_u32(dsm);
    const int tid = threadIdx.x;
    const int wid = tid >> 5;
    const int lane = tid & 31;
    const int warp_m = wid >> 2;
    const int warp_n = wid & 3;
    const int bm = blockIdx.y * 128;
    const int bn = blockIdx.x * 128;

    constexpr int TILE = 10240;  // 128 rows * 80 B
    constexpr int STAGE = 4 * TILE;

    auto load_stage = [&](int st, int k0) {
        const uint32_t sb = sbase + st * STAGE;
#pragma unroll
        for (int j = 0; j < 2; j++) {
            const int i = tid + j * 256;
            const int r = i >> 2, q = i & 3;
            const uint32_t so = r * 80 + q * 16;
            const size_t ga = (size_t)(bm + r) * K + k0 + q * 8;
            const size_t gw = (size_t)(bn + r) * K + k0 + q * 8;
            cp16(sb + 0 * TILE + so, Ah + ga);
            cp16(sb + 1 * TILE + so, Al + ga);
            cp16(sb + 2 * TILE + so, Wh + gw);
            cp16(sb + 3 * TILE + so, Wl + gw);
        }
    };

    float acc[4][4][4];
#pragma unroll
    for (int mt = 0; mt < 4; mt++)
#pragma unroll
        for (int nt = 0; nt < 4; nt++)
#pragma unroll
            for (int e = 0; e < 4; e++) acc[mt][nt][e] = 0.f;

    const int nc = K >> 5;
    load_stage(0, 0);
    CP_COMMIT();

    const int a_row = lane & 15;
    const int a_kc8 = (lane >> 4) * 8;
    const int b_row = (lane & 7) + ((lane >> 4) & 1) * 8;
    const int b_kc8 = ((lane >> 3) & 1) * 8;

    for (int c = 0; c < nc; c++) {
        if (c + 1 < nc) {
            load_stage((c + 1) & 1, (c + 1) << 5);
            CP_COMMIT();
            CP_WAIT(1);
        } else {
            CP_WAIT(0);
        }
        __syncthreads();

        const uint32_t sb = sbase + (c & 1) * STAGE;
#pragma unroll
        for (int ks = 0; ks < 2; ks++) {
            const int kc = ks * 16;
            uint32_t af[4][4], whf[2][4], wlf[2][4];
#pragma unroll
            for (int mt = 0; mt < 4; mt++)
                ldsm4(af[mt], sb + 0 * TILE +
                              (warp_m * 64 + mt * 16 + a_row) * 80 +
                              (kc + a_kc8) * 2);
#pragma unroll
            for (int p = 0; p < 2; p++) {
                const uint32_t boff = (warp_n * 32 + p * 16 + b_row) * 80 +
                                      (kc + b_kc8) * 2;
                ldsm4(whf[p], sb + 2 * TILE + boff);
                ldsm4(wlf[p], sb + 3 * TILE + boff);
            }
#pragma unroll
            for (int mt = 0; mt < 4; mt++)
#pragma unroll
                for (int nt = 0; nt < 4; nt++)
                    mma16816(acc[mt][nt], af[mt], whf[nt >> 1][(nt & 1) * 2],
                             whf[nt >> 1][(nt & 1) * 2 + 1]);
#pragma unroll
            for (int mt = 0; mt < 4; mt++)
#pragma unroll
                for (int nt = 0; nt < 4; nt++)
                    mma16816(acc[mt][nt], af[mt], wlf[nt >> 1][(nt & 1) * 2],
                             wlf[nt >> 1][(nt & 1) * 2 + 1]);
#pragma unroll
            for (int mt = 0; mt < 4; mt++)
                ldsm4(af[mt], sb + 1 * TILE +
                              (warp_m * 64 + mt * 16 + a_row) * 80 +
                              (kc + a_kc8) * 2);
#pragma unroll
            for (int mt = 0; mt < 4; mt++)
#pragma unroll
                for (int nt = 0; nt < 4; nt++)
                    mma16816(acc[mt][nt], af[mt], whf[nt >> 1][(nt & 1) * 2],
                             whf[nt >> 1][(nt & 1) * 2 + 1]);
        }
        __syncthreads();
    }

#pragma unroll
    for (int mt = 0; mt < 4; mt++) {
#pragma unroll
        for (int nt = 0; nt < 4; nt++) {
            const int col = bn + warp_n * 32 + nt * 8 + (lane & 3) * 2;
            const int r0 = bm + warp_m * 64 + mt * 16 + (lane >> 2);
            const int r1 = r0 + 8;
            float v0 = acc[mt][nt][0] + bias[col];
            float v1 = acc[mt][nt][1] + bias[col + 1];
            float v2 = acc[mt][nt][2] + bias[col];
            float v3 = acc[mt][nt][3] + bias[col + 1];
            if constexpr (RELU) {
                v0 = fmaxf(v0, 0.f); v1 = fmaxf(v1, 0.f);
                v2 = fmaxf(v2, 0.f); v3 = fmaxf(v3, 0.f);
            }
            if constexpr (RES) {
                v0 += res[(size_t)r0 * N + col];
                v1 += res[(size_t)r0 * N + col + 1];
                v2 += res[(size_t)r1 * N + col];
                v3 += res[(size_t)r1 * N + col + 1];
            }
            if constexpr (OSPLIT) {
                __nv_bfloat16 h0 = __float2bfloat16(v0), h1 = __float2bfloat16(v1);
                __nv_bfloat16 h2 = __float2bfloat16(v2), h3 = __float2bfloat16(v3);
                *reinterpret_cast<__nv_bfloat162*>(Ch + (size_t)r0 * N + col) =
                    __nv_bfloat162(h0, h1);
                *reinterpret_cast<__nv_bfloat162*>(Ch + (size_t)r1 * N + col) =
                    __nv_bfloat162(h2, h3);
                *reinterpret_cast<__nv_bfloat162*>(Cl + (size_t)r0 * N + col) =
                    __nv_bfloat162(__float2bfloat16(v0 - __bfloat162float(h0)),
                                   __float2bfloat16(v1 - __bfloat162float(h1)));
                *reinterpret_cast<__nv_bfloat162*>(Cl + (size_t)r1 * N + col) =
                    __nv_bfloat162(__float2bfloat16(v2 - __bfloat162float(h2)),
                                   __float2bfloat16(v3 - __bfloat162float(h3)));
            } else {
                *reinterpret_cast<float2*>(C + (size_t)r0 * N + col) =
                    make_float2(v0, v1);
                *reinterpret_cast<float2*>(C + (size_t)r1 * N + col) =
                    make_float2(v2, v3);
            }
        }
    }
}

// ---------------------------------------------------------------------------
// Tensor-core flash attention. Grid 128 = (b, h, qtile128, split2), 256 thr.
// Warp w owns q-rows [w*16, w*16+16). Per 64-key chunk: S = Q K^T (mma),
// bias+mask+online softmax in regs, P (regs, bf16) @ V (ldsm.trans) -> O.
// Partials (o, m, l) to gmem; combine kernel normalizes.
// ---------------------------------------------------------------------------
constexpr int STR = 72;  // halves per smem row (144 B)

__global__ void __launch_bounds__(256) attn_mma_kernel(
    const int* __restrict__ qx, const int* __restrict__ qy,
    const void* __restrict__ qpm,
    const int* __restrict__ axp, const int* __restrict__ ayp,
    const void* __restrict__ apm,
    const void* __restrict__ fmask, const void* __restrict__ padm,
    const float* __restrict__ pex, const float* __restrict__ pey)
{
    __shared__ __nv_bfloat16 Qs[128 * STR];
    __shared__ __nv_bfloat16 Ks[64 * STR];
    __shared__ __nv_bfloat16 Vs[64 * STR];
    __shared__ float pexh[2 * MD + 1], peyh[2 * MD + 1];
    __shared__ int sax[64], say[64];
    __shared__ float sam[64];
    __shared__ unsigned char spad[64];
    __shared__ int sqxv[128], sqyv[128];
    __shared__ float sqm[128];

    const int tid = threadIdx.x;
    const int wid = tid >> 5;
    const int lane = tid & 31;
    const int blk = blockIdx.x;
    const int s = blk & 1;
    const int qt = (blk >> 1) & 3;
    const int h = (blk >> 3) & 7;
    const int b = blk >> 6;
    const int q0 = qt * 128;
    const int bh = b * H + h;
    const int mb = g_mask_is_byte;
    const int abase = s * (A / 2);

    // per-head pos tables + q-side attrs + Q tile (bf16)
    for (int i = tid; i < 2 * MD + 1; i += 256) {
        pexh[i] = pex[i * H + h];
        peyh[i] = pey[i * H + h];
    }
    if (tid < 128) {
        const int qg = b * Q + q0 + tid;
        sqxv[tid] = qx[qg];
        sqyv[tid] = qy[qg];
        sqm[tid] = mask_at(qpm, qg, mb) ? 1.f : 0.f;
    }
#pragma unroll
    for (int j = 0; j < 8; j++) {
        const int i = tid + j * 256;
        const int r = i >> 4, c4 = i & 15;
        float4 v = *reinterpret_cast<const float4*>(
            &g_q[((size_t)(b * Q + q0 + r)) * D + h * DK + c4 * 4]);
        *reinterpret_cast<uint2*>(&Qs[r * STR + c4 * 4]) =
            make_uint2(pack_bf(v.x, v.y), pack_bf(v.z, v.w));
    }
    __syncthreads();

    // Q fragments (loop-invariant)
    const uint32_t qsb = smem_u32(Qs);
    const uint32_t ksb = smem_u32(Ks);
    const uint32_t vsb = smem_u32(Vs);
    const int a_row = lane & 15;
    const int a_k8 = (lane >> 4) * 8;
    const int b_row = (lane & 7) + ((lane >> 4) & 1) * 8;
    const int b_k8 = ((lane >> 3) & 1) * 8;
    const int vt_row = (lane & 7) + ((lane >> 3) & 1) * 8;
    const int vt_c8 = ((lane >> 4) & 1) * 8;
    uint32_t qf[4][4];
#pragma unroll
    for (int kb = 0; kb < 4; kb++)
        ldsm4(qf[kb], qsb + ((wid * 16 + a_row) * STR + kb * 16 + a_k8) * 2);

    const int r0 = lane >> 2;

    float of[8][4];
#pragma unroll
    for (int nt = 0; nt < 8; nt++)
#pragma unroll
        for (int e = 0; e < 4; e++) of[nt][e] = 0.f;
    float m2[2] = {-1e30f, -1e30f}, l2[2] = {0.f, 0.f};

    // prefetch chunk 0 (K/V fp32 + a-side attrs)
    float4 kf[4], vf[4];
    int pax = 0, pay = 0;
    float pam = 0.f;
    unsigned char ppad = 0;
    {
        const int a0 = abase;
#pragma unroll
        for (int j = 0; j < 4; j++) {
            const int i = tid + j * 256;
            const int r = i >> 4, c4 = i & 15;
            const size_t gi = ((size_t)(b * A + a0 + r)) * D + h * DK + c4 * 4;
            kf[j] = *reinterpret_cast<const float4*>(&g_k[gi]);
            vf[j] = *reinterpret_cast<const float4*>(&g_v[gi]);
        }
        if (tid < 64) {
            const int ag = b * A + a0 + tid;
            pax = axp[ag]; pay = ayp[ag];
            pam = mask_at(apm, ag, mb) ? 1.f : 0.f;
            ppad = mask_at(padm, ag, mb) ? 1 : 0;
        }
    }

    const int nchunks = (A / 2) / 64;  // 32
    for (int c = 0; c < nchunks; c++) {
        __syncthreads();  // prior compute done; smem writable
        // store prefetched chunk to smem (bf16)
#pragma unroll
        for (int j = 0; j < 4; j++) {
            const int i = tid + j * 256;
            const int r = i >> 4, c4 = i & 15;
            *reinterpret_cast<uint2*>(&Ks[r * STR + c4 * 4]) =
                make_uint2(pack_bf(kf[j].x, kf[j].y), pack_bf(kf[j].z, kf[j].w));
            *reinterpret_cast<uint2*>(&Vs[r * STR + c4 * 4]) =
                make_uint2(pack_bf(vf[j].x, vf[j].y), pack_bf(vf[j].z, vf[j].w));
        }
        if (tid < 64) {
            sax[tid] = pax; say[tid] = pay;
            sam[tid] = pam; spad[tid] = ppad;
        }
        __syncthreads();

        const int a0 = abase + c * 64;
        // prefetch next chunk
        if (c + 1 < nchunks) {
            const int a1 = a0 + 64;
#pragma unroll
            for (int j = 0; j < 4; j++) {
                const int i = tid + j * 256;
                const int r = i >> 4, c4 = i & 15;
                const size_t gi = ((size_t)(b * A + a1 + r)) * D + h * DK + c4 * 4;
                kf[j] = *reinterpret_cast<const float4*>(&g_k[gi]);
                vf[j] = *reinterpret_cast<const float4*>(&g_v[gi]);
            }
            if (tid < 64) {
                const int ag = b * A + a1 + tid;
                pax = axp[ag]; pay = ayp[ag];
                pam = mask_at(apm, ag, mb) ? 1.f : 0.f;
                ppad = mask_at(padm, ag, mb) ? 1 : 0;
            }
        }

        // fmask prefetch (byte path) — 2 rows x 8 col-pairs
        uint32_t fmr[2][8];
        if (mb) {
            const unsigned char* fp = (const unsigned char*)fmask;
#pragma unroll
            for (int rr = 0; rr < 2; rr++) {
                const size_t fb =
                    ((size_t)(b * Q + q0 + wid * 16 + r0 + rr * 8)) * A + a0 +
                    (lane & 3) * 2;
#pragma unroll
                for (int nt = 0; nt < 8; nt++)
                    fmr[rr][nt] =
                        *reinterpret_cast<const unsigned short*>(fp + fb + nt * 8);
            }
        }

        // S = Q K^T
        float sacc[8][4];
#pragma unroll
        for (int nt = 0; nt < 8; nt++)
#pragma unroll
            for (int e = 0; e < 4; e++) sacc[nt][e] = 0.f;
#pragma unroll
        for (int nt16 = 0; nt16 < 4; nt16++) {
#pragma unroll
            for (int kb = 0; kb < 4; kb++) {
                uint32_t kfr[4];
                ldsm4(kfr, ksb + ((nt16 * 16 + b_row) * STR + kb * 16 + b_k8) * 2);
                mma16816(sacc[2 * nt16], qf[kb], kfr[0], kfr[1]);
                mma16816(sacc[2 * nt16 + 1], qf[kb], kfr[2], kfr[3]);
            }
        }

        // bias + masks + online softmax (rows r0, r0+8)
#pragma unroll
        for (int rr = 0; rr < 2; rr++) {
            const int ql = wid * 16 + r0 + rr * 8;
            const int qxv = sqxv[ql], qyv = sqyv[ql];
            const float qm = sqm[ql];
            float mt = -1e30f;
#pragma unroll
            for (int nt = 0; nt < 8; nt++) {
#pragma unroll
                for (int e = 0; e < 2; e++) {
                    const int ac = nt * 8 + (lane & 3) * 2 + e;
                    int rx = qxv - sax[ac];
                    rx = max(-MD, min(MD, rx)) + MD;
                    int ry = qyv - say[ac];
                    ry = max(-MD, min(MD, ry)) + MD;
                    const float bias = (pexh[rx] + peyh[ry]) * (qm * sam[ac]);
                    float sc = fmaf(sacc[nt][rr * 2 + e], 0.125f, bias);
                    bool fm;
                    if (mb) fm = ((fmr[rr][nt] >> (e * 8)) & 0xffu) != 0u;
                    else
                        fm = mask_at(fmask,
                                     ((size_t)(b * Q + q0 + ql)) * A + a0 + ac, 0);
                    if (!fm || spad[ac]) sc = NEG;
                    sacc[nt][rr * 2 + e] = sc;
                    mt = fmaxf(mt, sc);
                }
            }
            mt = fmaxf(mt, __shfl_xor_sync(0xffffffffu, mt, 1));
            mt = fmaxf(mt, __shfl_xor_sync(0xffffffffu, mt, 2));
            const float mn = fmaxf(m2[rr], mt);
            const float scale = __expf(m2[rr] - mn);
            m2[rr] = mn;
            float rs = 0.f;
#pragma unroll
            for (int nt = 0; nt < 8; nt++) {
#pragma unroll
                for (int e = 0; e < 2; e++) {
                    const float p = __expf(sacc[nt][rr * 2 + e] - mn);
                    sacc[nt][rr * 2 + e] = p;
                    rs += p;
                }
            }
            rs += __shfl_xor_sync(0xffffffffu, rs, 1);
            rs += __shfl_xor_sync(0xffffffffu, rs, 2);
            l2[rr] = l2[rr] * scale + rs;
#pragma unroll
            for (int nt = 0; nt < 8; nt++) {
                of[nt][rr * 2 + 0] *= scale;
                of[nt][rr * 2 + 1] *= scale;
            }
        }

        // pack P to A-fragments (bf16)
        uint32_t pf[4][4];
#pragma unroll
        for (int kb = 0; kb < 4; kb++) {
            pf[kb][0] = pack_bf(sacc[2 * kb][0], sacc[2 * kb][1]);
            pf[kb][1] = pack_bf(sacc[2 * kb][2], sacc[2 * kb][3]);
            pf[kb][2] = pack_bf(sacc[2 * kb + 1][0], sacc[2 * kb + 1][1]);
            pf[kb][3] = pack_bf(sacc[2 * kb + 1][2], sacc[2 * kb + 1][3]);
        }

        // O += P V  (V via ldmatrix.trans)
#pragma unroll
        for (int dt16 = 0; dt16 < 4; dt16++) {
#pragma unroll
            for (int kb = 0; kb < 4; kb++) {
                uint32_t vfr[4];
                ldsm4t(vfr, vsb + ((kb * 16 + vt_row) * STR + dt16 * 16 + vt_c8) * 2);
                mma16816(of[2 * dt16], pf[kb], vfr[0], vfr[1]);
                mma16816(of[2 * dt16 + 1], pf[kb], vfr[2], vfr[3]);
            }
        }
    }

    // write partials (unnormalized o, m, l)
    const int prow0 = bh * Q + q0 + wid * 16 + r0;
#pragma unroll
    for (int nt = 0; nt < 8; nt++) {
        const int d = nt * 8 + (lane & 3) * 2;
        *reinterpret_cast<float2*>(&g_po[s][(size_t)prow0 * DK + d]) =
            make_float2(of[nt][0], of[nt][1]);
        *reinterpret_cast<float2*>(&g_po[s][(size_t)(prow0 + 8) * DK + d]) =
            make_float2(of[nt][2], of[nt][3]);
    }
    if ((lane & 3) == 0) {
        g_pm[s][prow0] = m2[0];
        g_pm[s][prow0 + 8] = m2[1];
        g_pl[s][prow0] = l2[0];
        g_pl[s][prow0 + 8] = l2[1];
    }
}

// combine split-A partials -> ctx (directly as bf16 hi/lo, layout [b,q,h*64+d])
__global__ void __launch_bounds__(256) attn_combine_kernel(
    __nv_bfloat16* __restrict__ ctx_h, __nv_bfloat16* __restrict__ ctx_l)
{
    const int e = blockIdx.x * 256 + threadIdx.x;  // B*H*Q*DK elements
    const int row = e >> 6;
    const int d = e & 63;
    const float m0 = g_pm[0][row], m1 = g_pm[1][row];
    const float mx = fmaxf(m0, m1);
    const float w0 = __expf(m0 - mx), w1 = __expf(m1 - mx);
    const float l = g_pl[0][row] * w0 + g_pl[1][row] * w1;
    const float v =
        (g_po[0][(size_t)row * DK + d] * w0 + g_po[1][(size_t)row * DK + d] * w1) / l;
    const int bq = row >> 12;              // b
    const int hh = (row >> 9) & 7;         // h
    const int qq = row & 511;              // q
    const size_t idx = ((size_t)(bq * Q + qq)) * D + hh * DK + d;
    const __nv_bfloat16 hi = __float2bfloat16(v);
    ctx_h[idx] = hi;
    ctx_l[idx] = __float2bfloat16(v - __bfloat162float(hi));
}

// ---------------------------------------------------------------------------
// LayerNorm over rows of length D=512; optional fused bf16 hi/lo output.
// ---------------------------------------------------------------------------
__global__ void __launch_bounds__(256) layernorm_kernel(
    const float* __restrict__ x, const float* __restrict__ gw,
    const float* __restrict__ bw, float* __restrict__ out,
    __nv_bfloat16* __restrict__ oh, __nv_bfloat16* __restrict__ ol)
{
    __shared__ float red[8];
    const int row = blockIdx.x;
    const int tid = threadIdx.x;
    const float* xr = x + (size_t)row * D;
    const float v0 = xr[tid];
    const float v1 = xr[tid + 256];

    float s = v0 + v1;
#pragma unroll
    for (int off = 16; off; off >>= 1) s += __shfl_xor_sync(0xffffffffu, s, off);
    if ((tid & 31) == 0) red[tid >> 5] = s;
    __syncthreads();
    float tot = 0.f;
#pragma unroll
    for (int i = 0; i < 8; i++) tot += red[i];
    const float mean = tot * (1.f / D);
    const float d0 = v0 - mean, d1 = v1 - mean;
    __syncthreads();

    float s2 = d0 * d0 + d1 * d1;
#pragma unroll
    for (int off = 16; off; off >>= 1) s2 += __shfl_xor_sync(0xffffffffu, s2, off);
    if ((tid & 31) == 0) red[tid >> 5] = s2;
    __syncthreads();
    float tot2 = 0.f;
#pragma unroll
    for (int i = 0; i < 8; i++) tot2 += red[i];
    const float inv = rsqrtf(tot2 * (1.f / D) + 1e-5f);

    const float o0 = d0 * inv * gw[tid] + bw[tid];
    const float o1 = d1 * inv * gw[tid + 256] + bw[tid + 256];
    out[(size_t)row * D + tid] = o0;
    out[(size_t)row * D + tid + 256] = o1;
    if (oh) {
        const __nv_bfloat16 h0 = __float2bfloat16(o0);
        const __nv_bfloat16 h1 = __float2bfloat16(o1);
        oh[(size_t)row * D + tid] = h0;
        oh[(size_t)row * D + tid + 256] = h1;
        ol[(size_t)row * D + tid] = __float2bfloat16(o0 - __bfloat162float(h0));
        ol[(size_t)row * D + tid + 256] =
            __float2bfloat16(o1 - __bfloat162float(h1));
    }
}

// ---------------------------------------------------------------------------
extern "C" void kernel_launch(void* const* d_in, const int* in_sizes, int n_in,
                              void* d_out, int out_size)
{
    const float* query_tokens = (const float*)d_in[0];
    const int* qx = (const int*)d_in[1];
    const int* qy = (const int*)d_in[2];
    const void* qpm = d_in[3];
    const float* all_tokens = (const float*)d_in[4];
    const int* ax = (const int*)d_in[5];
    const int* ay = (const int*)d_in[6];
    const void* apm = d_in[7];
    const void* fmask = d_in[8];
    const void* padm = d_in[9];
    const float* Wq = (const float*)d_in[10];
    const float* bq = (const float*)d_in[11];
    const float* Wk = (const float*)d_in[12];
    const float* bk = (const float*)d_in[13];
    const float* Wv = (const float*)d_in[14];
    const float* bv = (const float*)d_in[15];
    const float* Wo = (const float*)d_in[16];
    const float* bo = (const float*)d_in[17];
    const float* pex = (const float*)d_in[18];
    const float* pey = (const float*)d_in[19];
    const float* W1 = (const float*)d_in[20];
    const float* b1 = (const float*)d_in[21];
    const float* W2 = (const float*)d_in[22];
    const float* b2 = (const float*)d_in[23];
    const float* g1 = (const float*)d_in[24];
    const float* be1 = (const float*)d_in[25];
    const float* g2 = (const float*)d_in[26];
    const float* be2 = (const float*)d_in[27];
    float* out = (float*)d_out;

    float *pq, *pk, *pv, *pres1, *px1, *pres2;
    cudaGetSymbolAddress((void**)&pq, g_q);
    cudaGetSymbolAddress((void**)&pk, g_k);
    cudaGetSymbolAddress((void**)&pv, g_v);
    cudaGetSymbolAddress((void**)&pres1, g_res1);
    cudaGetSymbolAddress((void**)&px1, g_x1);
    cudaGetSymbolAddress((void**)&pres2, g_res2);

    __nv_bfloat16 *qt_h, *qt_l, *at_h, *at_l, *ctx_h, *ctx_l, *x1_h, *x1_l,
        *ff1_h, *ff1_l;
    __nv_bfloat16 *wq_h, *wq_l, *wk_h, *wk_l, *wv_h, *wv_l, *wo_h, *wo_l,
        *w1_h, *w1_l, *w2_h, *w2_l;
    cudaGetSymbolAddress((void**)&qt_h, b_qt_h);
    cudaGetSymbolAddress((void**)&qt_l, b_qt_l);
    cudaGetSymbolAddress((void**)&at_h, b_at_h);
    cudaGetSymbolAddress((void**)&at_l, b_at_l);
    cudaGetSymbolAddress((void**)&ctx_h, b_ctx_h);
    cudaGetSymbolAddress((void**)&ctx_l, b_ctx_l);
    cudaGetSymbolAddress((void**)&x1_h, b_x1_h);
    cudaGetSymbolAddress((void**)&x1_l, b_x1_l);
    cudaGetSymbolAddress((void**)&ff1_h, b_ff1_h);
    cudaGetSymbolAddress((void**)&ff1_l, b_ff1_l);
    cudaGetSymbolAddress((void**)&wq_h, b_wq_h);
    cudaGetSymbolAddress((void**)&wq_l, b_wq_l);
    cudaGetSymbolAddress((void**)&wk_h, b_wk_h);
    cudaGetSymbolAddress((void**)&wk_l, b_wk_l);
    cudaGetSymbolAddress((void**)&wv_h, b_wv_h);
    cudaGetSymbolAddress((void**)&wv_l, b_wv_l);
    cudaGetSymbolAddress((void**)&wo_h, b_wo_h);
    cudaGetSymbolAddress((void**)&wo_l, b_wo_l);
    cudaGetSymbolAddress((void**)&w1_h, b_w1_h);
    cudaGetSymbolAddress((void**)&w1_l, b_w1_l);
    cudaGetSymbolAddress((void**)&w2_h, b_w2_h);
    cudaGetSymbolAddress((void**)&w2_l, b_w2_l);

    const int gemm_smem = 2 * 4 * 10240;  // 81920
    cudaFuncSetAttribute(gemm_mma<false, false, false>,
                         cudaFuncAttributeMaxDynamicSharedMemorySize, gemm_smem);
    cudaFuncSetAttribute(gemm_mma<false, true, false>,
                         cudaFuncAttributeMaxDynamicSharedMemorySize, gemm_smem);
    cudaFuncSetAttribute(gemm_mma<true, false, true>,
                         cudaFuncAttributeMaxDynamicSharedMemorySize, gemm_smem);

    auto split = [](const float* x, __nv_bfloat16* h, __nv_bfloat16* l, int n) {
        int n4 = n / 4;
        int blocks = (n4 + 255) / 256;
        if (blocks > 1024) blocks = 1024;
        split_kernel<<<blocks, 256>>>(x, h, l, n4);
    };

    // 0. mask dtype detect
    detect_mask_kernel<<<1, 1>>>((const unsigned int*)fmask);

    // 1. split inputs + weights to bf16 hi/lo
    split(query_tokens, qt_h, qt_l, B * Q * D);
    split(all_tokens, at_h, at_l, B * A * D);
    split(Wq, wq_h, wq_l, D * D);
    split(Wk, wk_h, wk_l, D * D);
    split(Wv, wv_h, wv_l, D * D);
    split(Wo, wo_h, wo_l, D * D);
    split(W1, w1_h, w1_l, DFF * D);
    split(W2, w2_h, w2_l, D * DFF);

    // 2. projections
    gemm_mma<false, false, false><<<dim3(D / 128, (B * Q) / 128), 256, gemm_smem>>>(
        qt_h, qt_l, wq_h, wq_l, bq, nullptr, pq, nullptr, nullptr, B * Q, D, D);
    gemm_mma<false, false, false><<<dim3(D / 128, (B * A) / 128), 256, gemm_smem>>>(
        at_h, at_l, wk_h, wk_l, bk, nullptr, pk, nullptr, nullptr, B * A, D, D);
    gemm_mma<false, false, false><<<dim3(D / 128, (B * A) / 128), 256, gemm_smem>>>(
        at_h, at_l, wv_h, wv_l, bv, nullptr, pv, nullptr, nullptr, B * A, D, D);

    // 3. attention (tensor cores, split-A) + combine -> ctx hi/lo
    attn_mma_kernel<<<128, 256>>>(qx, qy, qpm, ax, ay, apm, fmask, padm, pex, pey);
    attn_combine_kernel<<<(B * H * Q * DK) / 256, 256>>>(ctx_h, ctx_l);

    // 4. output projection + residual
    gemm_mma<false, true, false><<<dim3(D / 128, (B * Q) / 128), 256, gemm_smem>>>(
        ctx_h, ctx_l, wo_h, wo_l, bo, query_tokens, pres1, nullptr, nullptr,
        B * Q, D, D);

    // 5. LN1 (fused split)
    layernorm_kernel<<<B * Q, 256>>>(pres1, g1, be1, px1, x1_h, x1_l);

    // 6. FFN up + relu (fused split output)
    gemm_mma<true, false, true><<<dim3(DFF / 128, (B * Q) / 128), 256, gemm_smem>>>(
        x1_h, x1_l, w1_h, w1_l, b1, nullptr, nullptr, ff1_h, ff1_l, B * Q, DFF, D);

    // 7. FFN down + residual
    gemm_mma<false, true, false><<<dim3(D / 128, (B * Q) / 128), 256, gemm_smem>>>(
        ff1_h, ff1_l, w2_h, w2_l, b2, px1, pres2, nullptr, nullptr, B * Q, D, DFF);

    // 8. LN2 -> output
    layernorm_kernel<<<B * Q, 256>>>(pres2, g2, be2, out, nullptr, nullptr);
}

// round 12
// speedup vs baseline: 1.0104x; 1.0104x over previous
#include <cuda_runtime.h>
#include <cuda_bf16.h>
#include <cstdint>

// ---------------------------------------------------------------------------
// RelPosQTransformerLayer — R9: tensor-core flash attention + mma GEMMs
//   B=2, Q=512, A=4096, D=512, H=8, DK=64, DFF=2048, MD=100
// ---------------------------------------------------------------------------

namespace cfg {
constexpr int B = 2, Q = 512, A = 4096, D = 512, H = 8, DK = 64, DFF = 2048, MD = 100;
constexpr float NEG = -1e9f;
}
using namespace cfg;

// ---------------- device scratch (allocation-free) ----------------
__device__ float g_q[B * Q * D];
__device__ float g_k[B * A * D];
__device__ float g_v[B * A * D];
__device__ float g_res1[B * Q * D];
__device__ float g_x1[B * Q * D];
__device__ float g_res2[B * Q * D];
__device__ int g_mask_is_byte;

// attention split-A partials (unnormalized)
__device__ float g_po[2][B * H * Q * DK];
__device__ float g_pm[2][B * H * Q];
__device__ float g_pl[2][B * H * Q];

// bf16 hi/lo split buffers
__device__ __nv_bfloat16 b_qt_h[B * Q * D], b_qt_l[B * Q * D];
__device__ __nv_bfloat16 b_at_h[B * A * D], b_at_l[B * A * D];
__device__ __nv_bfloat16 b_ctx_h[B * Q * D], b_ctx_l[B * Q * D];
__device__ __nv_bfloat16 b_x1_h[B * Q * D], b_x1_l[B * Q * D];
__device__ __nv_bfloat16 b_ff1_h[B * Q * DFF], b_ff1_l[B * Q * DFF];
__device__ __nv_bfloat16 b_wq_h[D * D], b_wq_l[D * D];
__device__ __nv_bfloat16 b_wk_h[D * D], b_wk_l[D * D];
__device__ __nv_bfloat16 b_wv_h[D * D], b_wv_l[D * D];
__device__ __nv_bfloat16 b_wo_h[D * D], b_wo_l[D * D];
__device__ __nv_bfloat16 b_w1_h[DFF * D], b_w1_l[DFF * D];
__device__ __nv_bfloat16 b_w2_h[D * DFF], b_w2_l[D * DFF];

// ---------------- small helpers ----------------
__global__ void detect_mask_kernel(const unsigned int* __restrict__ fm) {
    g_mask_is_byte = (*fm == 0x01010101u) ? 1 : 0;
}
__device__ __forceinline__ bool mask_at(const void* p, size_t i, int is_byte) {
    if (is_byte) return ((const unsigned char*)p)[i] != 0;
    return ((const unsigned int*)p)[i] != 0u;
}
__device__ __forceinline__ uint32_t pack_bf(float a, float b) {
    __nv_bfloat162 t = __float22bfloat162_rn(make_float2(a, b));
    return *reinterpret_cast<uint32_t*>(&t);
}

__global__ void __launch_bounds__(256) split_kernel(
    const float* __restrict__ x, __nv_bfloat16* __restrict__ hi,
    __nv_bfloat16* __restrict__ lo, int n4)
{
    for (int i = blockIdx.x * blockDim.x + threadIdx.x; i < n4;
         i += gridDim.x * blockDim.x) {
        float4 v = reinterpret_cast<const float4*>(x)[i];
        __nv_bfloat16 h0 = __float2bfloat16(v.x);
        __nv_bfloat16 h1 = __float2bfloat16(v.y);
        __nv_bfloat16 h2 = __float2bfloat16(v.z);
        __nv_bfloat16 h3 = __float2bfloat16(v.w);
        __nv_bfloat16 l0 = __float2bfloat16(v.x - __bfloat162float(h0));
        __nv_bfloat16 l1 = __float2bfloat16(v.y - __bfloat162float(h1));
        __nv_bfloat16 l2 = __float2bfloat16(v.z - __bfloat162float(h2));
        __nv_bfloat16 l3 = __float2bfloat16(v.w - __bfloat162float(h3));
        reinterpret_cast<__nv_bfloat162*>(hi)[i * 2 + 0] = __nv_bfloat162(h0, h1);
        reinterpret_cast<__nv_bfloat162*>(hi)[i * 2 + 1] = __nv_bfloat162(h2, h3);
        reinterpret_cast<__nv_bfloat162*>(lo)[i * 2 + 0] = __nv_bfloat162(l0, l1);
        reinterpret_cast<__nv_bfloat162*>(lo)[i * 2 + 1] = __nv_bfloat162(l2, l3);
    }
}

// ---------------- mma.sync / ldmatrix / cp.async wrappers ----------------
__device__ __forceinline__ uint32_t smem_u32(const void* p) {
    return (uint32_t)__cvta_generic_to_shared(p);
}
__device__ __forceinline__ void ldsm4(uint32_t r[4], uint32_t addr) {
    asm volatile(
        "ldmatrix.sync.aligned.m8n8.x4.shared.b16 {%0,%1,%2,%3}, [%4];"
        : "=r"(r[0]), "=r"(r[1]), "=r"(r[2]), "=r"(r[3])
        : "r"(addr));
}
__device__ __forceinline__ void ldsm4t(uint32_t r[4], uint32_t addr) {
    asm volatile(
        "ldmatrix.sync.aligned.m8n8.x4.trans.shared.b16 {%0,%1,%2,%3}, [%4];"
        : "=r"(r[0]), "=r"(r[1]), "=r"(r[2]), "=r"(r[3])
        : "r"(addr));
}
__device__ __forceinline__ void mma16816(float c[4], const uint32_t a[4],
                                         uint32_t b0, uint32_t b1) {
    asm volatile(
        "mma.sync.aligned.m16n8k16.row.col.f32.bf16.bf16.f32 "
        "{%0,%1,%2,%3}, {%4,%5,%6,%7}, {%8,%9}, {%0,%1,%2,%3};"
        : "+f"(c[0]), "+f"(c[1]), "+f"(c[2]), "+f"(c[3])
        : "r"(a[0]), "r"(a[1]), "r"(a[2]), "r"(a[3]), "r"(b0), "r"(b1));
}
__device__ __forceinline__ void cp16(uint32_t saddr, const void* g) {
    asm volatile("cp.async.cg.shared.global [%0], [%1], 16;"
                 :: "r"(saddr), "l"(g) : "memory");
}
#define CP_COMMIT() asm volatile("cp.async.commit_group;" ::: "memory")
#define CP_WAIT(n) asm volatile("cp.async.wait_group %0;" :: "n"(n) : "memory")

// ---------------------------------------------------------------------------
// mma.sync split-bf16 GEMM (from R4, validated). OSPLIT: write bf16 hi/lo.
// ---------------------------------------------------------------------------
template <bool RELU, bool RES, bool OSPLIT>
__global__ void __launch_bounds__(256, 2) gemm_mma(
    const __nv_bfloat16* __restrict__ Ah, const __nv_bfloat16* __restrict__ Al,
    const __nv_bfloat16* __restrict__ Wh, const __nv_bfloat16* __restrict__ Wl,
    const float* __restrict__ bias, const float* __restrict__ res,
    float* __restrict__ C, __nv_bfloat16* __restrict__ Ch,
    __nv_bfloat16* __restrict__ Cl, int M, int N, int K)
{
    extern __shared__ char dsm[];
    const uint32_t sbase = smem_u32(dsm);
    const int tid = threadIdx.x;
    const int wid = tid >> 5;
    const int lane = tid & 31;
    const int warp_m = wid >> 2;
    const int warp_n = wid & 3;
    const int bm = blockIdx.y * 128;
    const int bn = blockIdx.x * 128;

    constexpr int TILE = 10240;  // 128 rows * 80 B
    constexpr int STAGE = 4 * TILE;

    auto load_stage = [&](int st, int k0) {
        const uint32_t sb = sbase + st * STAGE;
#pragma unroll
        for (int j = 0; j < 2; j++) {
            const int i = tid + j * 256;
            const int r = i >> 2, q = i & 3;
            const uint32_t so = r * 80 + q * 16;
            const size_t ga = (size_t)(bm + r) * K + k0 + q * 8;
            const size_t gw = (size_t)(bn + r) * K + k0 + q * 8;
            cp16(sb + 0 * TILE + so, Ah + ga);
            cp16(sb + 1 * TILE + so, Al + ga);
            cp16(sb + 2 * TILE + so, Wh + gw);
            cp16(sb + 3 * TILE + so, Wl + gw);
        }
    };

    float acc[4][4][4];
#pragma unroll
    for (int mt = 0; mt < 4; mt++)
#pragma unroll
        for (int nt = 0; nt < 4; nt++)
#pragma unroll
            for (int e = 0; e < 4; e++) acc[mt][nt][e] = 0.f;

    const int nc = K >> 5;
    load_stage(0, 0);
    CP_COMMIT();

    const int a_row = lane & 15;
    const int a_kc8 = (lane >> 4) * 8;
    const int b_row = (lane & 7) + ((lane >> 4) & 1) * 8;
    const int b_kc8 = ((lane >> 3) & 1) * 8;

    for (int c = 0; c < nc; c++) {
        if (c + 1 < nc) {
            load_stage((c + 1) & 1, (c + 1) << 5);
            CP_COMMIT();
            CP_WAIT(1);
        } else {
            CP_WAIT(0);
        }
        __syncthreads();

        const uint32_t sb = sbase + (c & 1) * STAGE;
#pragma unroll
        for (int ks = 0; ks < 2; ks++) {
            const int kc = ks * 16;
            uint32_t af[4][4], whf[2][4], wlf[2][4];
#pragma unroll
            for (int mt = 0; mt < 4; mt++)
                ldsm4(af[mt], sb + 0 * TILE +
                              (warp_m * 64 + mt * 16 + a_row) * 80 +
                              (kc + a_kc8) * 2);
#pragma unroll
            for (int p = 0; p < 2; p++) {
                const uint32_t boff = (warp_n * 32 + p * 16 + b_row) * 80 +
                                      (kc + b_kc8) * 2;
                ldsm4(whf[p], sb + 2 * TILE + boff);
                ldsm4(wlf[p], sb + 3 * TILE + boff);
            }
#pragma unroll
            for (int mt = 0; mt < 4; mt++)
#pragma unroll
                for (int nt = 0; nt < 4; nt++)
                    mma16816(acc[mt][nt], af[mt], whf[nt >> 1][(nt & 1) * 2],
                             whf[nt >> 1][(nt & 1) * 2 + 1]);
#pragma unroll
            for (int mt = 0; mt < 4; mt++)
#pragma unroll
                for (int nt = 0; nt < 4; nt++)
                    mma16816(acc[mt][nt], af[mt], wlf[nt >> 1][(nt & 1) * 2],
                             wlf[nt >> 1][(nt & 1) * 2 + 1]);
#pragma unroll
            for (int mt = 0; mt < 4; mt++)
                ldsm4(af[mt], sb + 1 * TILE +
                              (warp_m * 64 + mt * 16 + a_row) * 80 +
                              (kc + a_kc8) * 2);
#pragma unroll
            for (int mt = 0; mt < 4; mt++)
#pragma unroll
                for (int nt = 0; nt < 4; nt++)
                    mma16816(acc[mt][nt], af[mt], whf[nt >> 1][(nt & 1) * 2],
                             whf[nt >> 1][(nt & 1) * 2 + 1]);
        }
        __syncthreads();
    }

#pragma unroll
    for (int mt = 0; mt < 4; mt++) {
#pragma unroll
        for (int nt = 0; nt < 4; nt++) {
            const int col = bn + warp_n * 32 + nt * 8 + (lane & 3) * 2;
            const int r0 = bm + warp_m * 64 + mt * 16 + (lane >> 2);
            const int r1 = r0 + 8;
            float v0 = acc[mt][nt][0] + bias[col];
            float v1 = acc[mt][nt][1] + bias[col + 1];
            float v2 = acc[mt][nt][2] + bias[col];
            float v3 = acc[mt][nt][3] + bias[col + 1];
            if constexpr (RELU) {
                v0 = fmaxf(v0, 0.f); v1 = fmaxf(v1, 0.f);
                v2 = fmaxf(v2, 0.f); v3 = fmaxf(v3, 0.f);
            }
            if constexpr (RES) {
                v0 += res[(size_t)r0 * N + col];
                v1 += res[(size_t)r0 * N + col + 1];
                v2 += res[(size_t)r1 * N + col];
                v3 += res[(size_t)r1 * N + col + 1];
            }
            if constexpr (OSPLIT) {
                __nv_bfloat16 h0 = __float2bfloat16(v0), h1 = __float2bfloat16(v1);
                __nv_bfloat16 h2 = __float2bfloat16(v2), h3 = __float2bfloat16(v3);
                *reinterpret_cast<__nv_bfloat162*>(Ch + (size_t)r0 * N + col) =
                    __nv_bfloat162(h0, h1);
                *reinterpret_cast<__nv_bfloat162*>(Ch + (size_t)r1 * N + col) =
                    __nv_bfloat162(h2, h3);
                *reinterpret_cast<__nv_bfloat162*>(Cl + (size_t)r0 * N + col) =
                    __nv_bfloat162(__float2bfloat16(v0 - __bfloat162float(h0)),
                                   __float2bfloat16(v1 - __bfloat162float(h1)));
                *reinterpret_cast<__nv_bfloat162*>(Cl + (size_t)r1 * N + col) =
                    __nv_bfloat162(__float2bfloat16(v2 - __bfloat162float(h2)),
                                   __float2bfloat16(v3 - __bfloat162float(h3)));
            } else {
                *reinterpret_cast<float2*>(C + (size_t)r0 * N + col) =
                    make_float2(v0, v1);
                *reinterpret_cast<float2*>(C + (size_t)r1 * N + col) =
                    make_float2(v2, v3);
            }
        }
    }
}

// ---------------------------------------------------------------------------
// Tensor-core flash attention. Grid 128 = (b, h, qtile128, split2), 256 thr.
// Warp w owns q-rows [w*16, w*16+16). Per 64-key chunk: S = Q K^T (mma),
// bias+mask+online softmax in regs, P (regs, bf16) @ V (ldsm.trans) -> O.
// Partials (o, m, l) to gmem; combine kernel normalizes.
// ---------------------------------------------------------------------------
constexpr int STR = 72;  // halves per smem row (144 B)

__global__ void __launch_bounds__(256) attn_mma_kernel(
    const int* __restrict__ qx, const int* __restrict__ qy,
    const void* __restrict__ qpm,
    const int* __restrict__ axp, const int* __restrict__ ayp,
    const void* __restrict__ apm,
    const void* __restrict__ fmask, const void* __restrict__ padm,
    const float* __restrict__ pex, const float* __restrict__ pey)
{
    __shared__ __nv_bfloat16 Qs[128 * STR];
    __shared__ __nv_bfloat16 Ks[64 * STR];
    __shared__ __nv_bfloat16 Vs[64 * STR];
    __shared__ float pexh[2 * MD + 1], peyh[2 * MD + 1];
    __shared__ int sax[64], say[64];
    __shared__ float sam[64];
    __shared__ unsigned char spad[64];
    __shared__ int sqxv[128], sqyv[128];
    __shared__ float sqm[128];

    const int tid = threadIdx.x;
    const int wid = tid >> 5;
    const int lane = tid & 31;
    const int blk = blockIdx.x;
    const int s = blk & 1;
    const int qt = (blk >> 1) & 3;
    const int h = (blk >> 3) & 7;
    const int b = blk >> 6;
    const int q0 = qt * 128;
    const int bh = b * H + h;
    const int mb = g_mask_is_byte;
    const int abase = s * (A / 2);

    // per-head pos tables + q-side attrs + Q tile (bf16)
    for (int i = tid; i < 2 * MD + 1; i += 256) {
        pexh[i] = pex[i * H + h];
        peyh[i] = pey[i * H + h];
    }
    if (tid < 128) {
        const int qg = b * Q + q0 + tid;
        sqxv[tid] = qx[qg];
        sqyv[tid] = qy[qg];
        sqm[tid] = mask_at(qpm, qg, mb) ? 1.f : 0.f;
    }
#pragma unroll
    for (int j = 0; j < 8; j++) {
        const int i = tid + j * 256;
        const int r = i >> 4, c4 = i & 15;
        float4 v = *reinterpret_cast<const float4*>(
            &g_q[((size_t)(b * Q + q0 + r)) * D + h * DK + c4 * 4]);
        *reinterpret_cast<uint2*>(&Qs[r * STR + c4 * 4]) =
            make_uint2(pack_bf(v.x, v.y), pack_bf(v.z, v.w));
    }
    __syncthreads();

    // Q fragments (loop-invariant)
    const uint32_t qsb = smem_u32(Qs);
    const uint32_t ksb = smem_u32(Ks);
    const uint32_t vsb = smem_u32(Vs);
    const int a_row = lane & 15;
    const int a_k8 = (lane >> 4) * 8;
    const int b_row = (lane & 7) + ((lane >> 4) & 1) * 8;
    const int b_k8 = ((lane >> 3) & 1) * 8;
    const int vt_row = (lane & 7) + ((lane >> 3) & 1) * 8;
    const int vt_c8 = ((lane >> 4) & 1) * 8;
    uint32_t qf[4][4];
#pragma unroll
    for (int kb = 0; kb < 4; kb++)
        ldsm4(qf[kb], qsb + ((wid * 16 + a_row) * STR + kb * 16 + a_k8) * 2);

    const int r0 = lane >> 2;

    float of[8][4];
#pragma unroll
    for (int nt = 0; nt < 8; nt++)
#pragma unroll
        for (int e = 0; e < 4; e++) of[nt][e] = 0.f;
    float m2[2] = {-1e30f, -1e30f}, l2[2] = {0.f, 0.f};

    // prefetch chunk 0 (K/V fp32 + a-side attrs)
    float4 kf[4], vf[4];
    int pax = 0, pay = 0;
    float pam = 0.f;
    unsigned char ppad = 0;
    {
        const int a0 = abase;
#pragma unroll
        for (int j = 0; j < 4; j++) {
            const int i = tid + j * 256;
            const int r = i >> 4, c4 = i & 15;
            const size_t gi = ((size_t)(b * A + a0 + r)) * D + h * DK + c4 * 4;
            kf[j] = *reinterpret_cast<const float4*>(&g_k[gi]);
            vf[j] = *reinterpret_cast<const float4*>(&g_v[gi]);
        }
        if (tid < 64) {
            const int ag = b * A + a0 + tid;
            pax = axp[ag]; pay = ayp[ag];
            pam = mask_at(apm, ag, mb) ? 1.f : 0.f;
            ppad = mask_at(padm, ag, mb) ? 1 : 0;
        }
    }

    const int nchunks = (A / 2) / 64;  // 32
    for (int c = 0; c < nchunks; c++) {
        __syncthreads();  // prior compute done; smem writable
        // store prefetched chunk to smem (bf16)
#pragma unroll
        for (int j = 0; j < 4; j++) {
            const int i = tid + j * 256;
            const int r = i >> 4, c4 = i & 15;
            *reinterpret_cast<uint2*>(&Ks[r * STR + c4 * 4]) =
                make_uint2(pack_bf(kf[j].x, kf[j].y), pack_bf(kf[j].z, kf[j].w));
            *reinterpret_cast<uint2*>(&Vs[r * STR + c4 * 4]) =
                make_uint2(pack_bf(vf[j].x, vf[j].y), pack_bf(vf[j].z, vf[j].w));
        }
        if (tid < 64) {
            sax[tid] = pax; say[tid] = pay;
            sam[tid] = pam; spad[tid] = ppad;
        }
        __syncthreads();

        const int a0 = abase + c * 64;
        // prefetch next chunk
        if (c + 1 < nchunks) {
            const int a1 = a0 + 64;
#pragma unroll
            for (int j = 0; j < 4; j++) {
                const int i = tid + j * 256;
                const int r = i >> 4, c4 = i & 15;
                const size_t gi = ((size_t)(b * A + a1 + r)) * D + h * DK + c4 * 4;
                kf[j] = *reinterpret_cast<const float4*>(&g_k[gi]);
                vf[j] = *reinterpret_cast<const float4*>(&g_v[gi]);
            }
            if (tid < 64) {
                const int ag = b * A + a1 + tid;
                pax = axp[ag]; pay = ayp[ag];
                pam = mask_at(apm, ag, mb) ? 1.f : 0.f;
                ppad = mask_at(padm, ag, mb) ? 1 : 0;
            }
        }

        // fmask prefetch (byte path) — 2 rows x 8 col-pairs
        uint32_t fmr[2][8];
        if (mb) {
            const unsigned char* fp = (const unsigned char*)fmask;
#pragma unroll
            for (int rr = 0; rr < 2; rr++) {
                const size_t fb =
                    ((size_t)(b * Q + q0 + wid * 16 + r0 + rr * 8)) * A + a0 +
                    (lane & 3) * 2;
#pragma unroll
                for (int nt = 0; nt < 8; nt++)
                    fmr[rr][nt] =
                        *reinterpret_cast<const unsigned short*>(fp + fb + nt * 8);
            }
        }

        // S = Q K^T
        float sacc[8][4];
#pragma unroll
        for (int nt = 0; nt < 8; nt++)
#pragma unroll
            for (int e = 0; e < 4; e++) sacc[nt][e] = 0.f;
#pragma unroll
        for (int nt16 = 0; nt16 < 4; nt16++) {
#pragma unroll
            for (int kb = 0; kb < 4; kb++) {
                uint32_t kfr[4];
                ldsm4(kfr, ksb + ((nt16 * 16 + b_row) * STR + kb * 16 + b_k8) * 2);
                mma16816(sacc[2 * nt16], qf[kb], kfr[0], kfr[1]);
                mma16816(sacc[2 * nt16 + 1], qf[kb], kfr[2], kfr[3]);
            }
        }

        // bias + masks + online softmax (rows r0, r0+8)
#pragma unroll
        for (int rr = 0; rr < 2; rr++) {
            const int ql = wid * 16 + r0 + rr * 8;
            const int qxv = sqxv[ql], qyv = sqyv[ql];
            const float qm = sqm[ql];
            float mt = -1e30f;
#pragma unroll
            for (int nt = 0; nt < 8; nt++) {
#pragma unroll
                for (int e = 0; e < 2; e++) {
                    const int ac = nt * 8 + (lane & 3) * 2 + e;
                    int rx = qxv - sax[ac];
                    rx = max(-MD, min(MD, rx)) + MD;
                    int ry = qyv - say[ac];
                    ry = max(-MD, min(MD, ry)) + MD;
                    const float bias = (pexh[rx] + peyh[ry]) * (qm * sam[ac]);
                    float sc = fmaf(sacc[nt][rr * 2 + e], 0.125f, bias);
                    bool fm;
                    if (mb) fm = ((fmr[rr][nt] >> (e * 8)) & 0xffu) != 0u;
                    else
                        fm = mask_at(fmask,
                                     ((size_t)(b * Q + q0 + ql)) * A + a0 + ac, 0);
                    if (!fm || spad[ac]) sc = NEG;
                    sacc[nt][rr * 2 + e] = sc;
                    mt = fmaxf(mt, sc);
                }
            }
            mt = fmaxf(mt, __shfl_xor_sync(0xffffffffu, mt, 1));
            mt = fmaxf(mt, __shfl_xor_sync(0xffffffffu, mt, 2));
            const float mn = fmaxf(m2[rr], mt);
            const float scale = __expf(m2[rr] - mn);
            m2[rr] = mn;
            float rs = 0.f;
#pragma unroll
            for (int nt = 0; nt < 8; nt++) {
#pragma unroll
                for (int e = 0; e < 2; e++) {
                    const float p = __expf(sacc[nt][rr * 2 + e] - mn);
                    sacc[nt][rr * 2 + e] = p;
                    rs += p;
                }
            }
            rs += __shfl_xor_sync(0xffffffffu, rs, 1);
            rs += __shfl_xor_sync(0xffffffffu, rs, 2);
            l2[rr] = l2[rr] * scale + rs;
#pragma unroll
            for (int nt = 0; nt < 8; nt++) {
                of[nt][rr * 2 + 0] *= scale;
                of[nt][rr * 2 + 1] *= scale;
            }
        }

        // pack P to A-fragments (bf16)
        uint32_t pf[4][4];
#pragma unroll
        for (int kb = 0; kb < 4; kb++) {
            pf[kb][0] = pack_bf(sacc[2 * kb][0], sacc[2 * kb][1]);
            pf[kb][1] = pack_bf(sacc[2 * kb][2], sacc[2 * kb][3]);
            pf[kb][2] = pack_bf(sacc[2 * kb + 1][0], sacc[2 * kb + 1][1]);
            pf[kb][3] = pack_bf(sacc[2 * kb + 1][2], sacc[2 * kb + 1][3]);
        }

        // O += P V  (V via ldmatrix.trans)
#pragma unroll
        for (int dt16 = 0; dt16 < 4; dt16++) {
#pragma unroll
            for (int kb = 0; kb < 4; kb++) {
                uint32_t vfr[4];
                ldsm4t(vfr, vsb + ((kb * 16 + vt_row) * STR + dt16 * 16 + vt_c8) * 2);
                mma16816(of[2 * dt16], pf[kb], vfr[0], vfr[1]);
                mma16816(of[2 * dt16 + 1], pf[kb], vfr[2], vfr[3]);
            }
        }
    }

    // write partials (unnormalized o, m, l)
    const int prow0 = bh * Q + q0 + wid * 16 + r0;
#pragma unroll
    for (int nt = 0; nt < 8; nt++) {
        const int d = nt * 8 + (lane & 3) * 2;
        *reinterpret_cast<float2*>(&g_po[s][(size_t)prow0 * DK + d]) =
            make_float2(of[nt][0], of[nt][1]);
        *reinterpret_cast<float2*>(&g_po[s][(size_t)(prow0 + 8) * DK + d]) =
            make_float2(of[nt][2], of[nt][3]);
    }
    if ((lane & 3) == 0) {
        g_pm[s][prow0] = m2[0];
        g_pm[s][prow0 + 8] = m2[1];
        g_pl[s][prow0] = l2[0];
        g_pl[s][prow0 + 8] = l2[1];
    }
}

// combine split-A partials -> ctx (directly as bf16 hi/lo, layout [b,q,h*64+d])
__global__ void __launch_bounds__(256) attn_combine_kernel(
    __nv_bfloat16* __restrict__ ctx_h, __nv_bfloat16* __restrict__ ctx_l)
{
    const int e = blockIdx.x * 256 + threadIdx.x;  // B*H*Q*DK elements
    const int row = e >> 6;
    const int d = e & 63;
    const float m0 = g_pm[0][row], m1 = g_pm[1][row];
    const float mx = fmaxf(m0, m1);
    const float w0 = __expf(m0 - mx), w1 = __expf(m1 - mx);
    const float l = g_pl[0][row] * w0 + g_pl[1][row] * w1;
    const float v =
        (g_po[0][(size_t)row * DK + d] * w0 + g_po[1][(size_t)row * DK + d] * w1) / l;
    const int bq = row >> 12;              // b
    const int hh = (row >> 9) & 7;         // h
    const int qq = row & 511;              // q
    const size_t idx = ((size_t)(bq * Q + qq)) * D + hh * DK + d;
    const __nv_bfloat16 hi = __float2bfloat16(v);
    ctx_h[idx] = hi;
    ctx_l[idx] = __float2bfloat16(v - __bfloat162float(hi));
}

// ---------------------------------------------------------------------------
// LayerNorm over rows of length D=512; optional fused bf16 hi/lo output.
// ---------------------------------------------------------------------------
__global__ void __launch_bounds__(256) layernorm_kernel(
    const float* __restrict__ x, const float* __restrict__ gw,
    const float* __restrict__ bw, float* __restrict__ out,
    __nv_bfloat16* __restrict__ oh, __nv_bfloat16* __restrict__ ol)
{
    __shared__ float red[8];
    const int row = blockIdx.x;
    const int tid = threadIdx.x;
    const float* xr = x + (size_t)row * D;
    const float v0 = xr[tid];
    const float v1 = xr[tid + 256];

    float s = v0 + v1;
#pragma unroll
    for (int off = 16; off; off >>= 1) s += __shfl_xor_sync(0xffffffffu, s, off);
    if ((tid & 31) == 0) red[tid >> 5] = s;
    __syncthreads();
    float tot = 0.f;
#pragma unroll
    for (int i = 0; i < 8; i++) tot += red[i];
    const float mean = tot * (1.f / D);
    const float d0 = v0 - mean, d1 = v1 - mean;
    __syncthreads();

    float s2 = d0 * d0 + d1 * d1;
#pragma unroll
    for (int off = 16; off; off >>= 1) s2 += __shfl_xor_sync(0xffffffffu, s2, off);
    if ((tid & 31) == 0) red[tid >> 5] = s2;
    __syncthreads();
    float tot2 = 0.f;
#pragma unroll
    for (int i = 0; i < 8; i++) tot2 += red[i];
    const float inv = rsqrtf(tot2 * (1.f / D) + 1e-5f);

    const float o0 = d0 * inv * gw[tid] + bw[tid];
    const float o1 = d1 * inv * gw[tid + 256] + bw[tid + 256];
    out[(size_t)row * D + tid] = o0;
    out[(size_t)row * D + tid + 256] = o1;
    if (oh) {
        const __nv_bfloat16 h0 = __float2bfloat16(o0);
        const __nv_bfloat16 h1 = __float2bfloat16(o1);
        oh[(size_t)row * D + tid] = h0;
        oh[(size_t)row * D + tid + 256] = h1;
        ol[(size_t)row * D + tid] = __float2bfloat16(o0 - __bfloat162float(h0));
        ol[(size_t)row * D + tid + 256] =
            __float2bfloat16(o1 - __bfloat162float(h1));
    }
}

// ---------------------------------------------------------------------------
extern "C" void kernel_launch(void* const* d_in, const int* in_sizes, int n_in,
                              void* d_out, int out_size)
{
    const float* query_tokens = (const float*)d_in[0];
    const int* qx = (const int*)d_in[1];
    const int* qy = (const int*)d_in[2];
    const void* qpm = d_in[3];
    const float* all_tokens = (const float*)d_in[4];
    const int* ax = (const int*)d_in[5];
    const int* ay = (const int*)d_in[6];
    const void* apm = d_in[7];
    const void* fmask = d_in[8];
    const void* padm = d_in[9];
    const float* Wq = (const float*)d_in[10];
    const float* bq = (const float*)d_in[11];
    const float* Wk = (const float*)d_in[12];
    const float* bk = (const float*)d_in[13];
    const float* Wv = (const float*)d_in[14];
    const float* bv = (const float*)d_in[15];
    const float* Wo = (const float*)d_in[16];
    const float* bo = (const float*)d_in[17];
    const float* pex = (const float*)d_in[18];
    const float* pey = (const float*)d_in[19];
    const float* W1 = (const float*)d_in[20];
    const float* b1 = (const float*)d_in[21];
    const float* W2 = (const float*)d_in[22];
    const float* b2 = (const float*)d_in[23];
    const float* g1 = (const float*)d_in[24];
    const float* be1 = (const float*)d_in[25];
    const float* g2 = (const float*)d_in[26];
    const float* be2 = (const float*)d_in[27];
    float* out = (float*)d_out;

    float *pq, *pk, *pv, *pres1, *px1, *pres2;
    cudaGetSymbolAddress((void**)&pq, g_q);
    cudaGetSymbolAddress((void**)&pk, g_k);
    cudaGetSymbolAddress((void**)&pv, g_v);
    cudaGetSymbolAddress((void**)&pres1, g_res1);
    cudaGetSymbolAddress((void**)&px1, g_x1);
    cudaGetSymbolAddress((void**)&pres2, g_res2);

    __nv_bfloat16 *qt_h, *qt_l, *at_h, *at_l, *ctx_h, *ctx_l, *x1_h, *x1_l,
        *ff1_h, *ff1_l;
    __nv_bfloat16 *wq_h, *wq_l, *wk_h, *wk_l, *wv_h, *wv_l, *wo_h, *wo_l,
        *w1_h, *w1_l, *w2_h, *w2_l;
    cudaGetSymbolAddress((void**)&qt_h, b_qt_h);
    cudaGetSymbolAddress((void**)&qt_l, b_qt_l);
    cudaGetSymbolAddress((void**)&at_h, b_at_h);
    cudaGetSymbolAddress((void**)&at_l, b_at_l);
    cudaGetSymbolAddress((void**)&ctx_h, b_ctx_h);
    cudaGetSymbolAddress((void**)&ctx_l, b_ctx_l);
    cudaGetSymbolAddress((void**)&x1_h, b_x1_h);
    cudaGetSymbolAddress((void**)&x1_l, b_x1_l);
    cudaGetSymbolAddress((void**)&ff1_h, b_ff1_h);
    cudaGetSymbolAddress((void**)&ff1_l, b_ff1_l);
    cudaGetSymbolAddress((void**)&wq_h, b_wq_h);
    cudaGetSymbolAddress((void**)&wq_l, b_wq_l);
    cudaGetSymbolAddress((void**)&wk_h, b_wk_h);
    cudaGetSymbolAddress((void**)&wk_l, b_wk_l);
    cudaGetSymbolAddress((void**)&wv_h, b_wv_h);
    cudaGetSymbolAddress((void**)&wv_l, b_wv_l);
    cudaGetSymbolAddress((void**)&wo_h, b_wo_h);
    cudaGetSymbolAddress((void**)&wo_l, b_wo_l);
    cudaGetSymbolAddress((void**)&w1_h, b_w1_h);
    cudaGetSymbolAddress((void**)&w1_l, b_w1_l);
    cudaGetSymbolAddress((void**)&w2_h, b_w2_h);
    cudaGetSymbolAddress((void**)&w2_l, b_w2_l);

    const int gemm_smem = 2 * 4 * 10240;  // 81920
    cudaFuncSetAttribute(gemm_mma<false, false, false>,
                         cudaFuncAttributeMaxDynamicSharedMemorySize, gemm_smem);
    cudaFuncSetAttribute(gemm_mma<false, true, false>,
                         cudaFuncAttributeMaxDynamicSharedMemorySize, gemm_smem);
    cudaFuncSetAttribute(gemm_mma<true, false, true>,
                         cudaFuncAttributeMaxDynamicSharedMemorySize, gemm_smem);

    auto split = [](const float* x, __nv_bfloat16* h, __nv_bfloat16* l, int n) {
        int n4 = n / 4;
        int blocks = (n4 + 255) / 256;
        if (blocks > 1024) blocks = 1024;
        split_kernel<<<blocks, 256>>>(x, h, l, n4);
    };

    // 0. mask dtype detect
    detect_mask_kernel<<<1, 1>>>((const unsigned int*)fmask);

    // 1. split inputs + weights to bf16 hi/lo
    split(query_tokens, qt_h, qt_l, B * Q * D);
    split(all_tokens, at_h, at_l, B * A * D);
    split(Wq, wq_h, wq_l, D * D);
    split(Wk, wk_h, wk_l, D * D);
    split(Wv, wv_h, wv_l, D * D);
    split(Wo, wo_h, wo_l, D * D);
    split(W1, w1_h, w1_l, DFF * D);
    split(W2, w2_h, w2_l, D * DFF);

    // 2. projections
    gemm_mma<false, false, false><<<dim3(D / 128, (B * Q) / 128), 256, gemm_smem>>>(
        qt_h, qt_l, wq_h, wq_l, bq, nullptr, pq, nullptr, nullptr, B * Q, D, D);
    gemm_mma<false, false, false><<<dim3(D / 128, (B * A) / 128), 256, gemm_smem>>>(
        at_h, at_l, wk_h, wk_l, bk, nullptr, pk, nullptr, nullptr, B * A, D, D);
    gemm_mma<false, false, false><<<dim3(D / 128, (B * A) / 128), 256, gemm_smem>>>(
        at_h, at_l, wv_h, wv_l, bv, nullptr, pv, nullptr, nullptr, B * A, D, D);

    // 3. attention (tensor cores, split-A) + combine -> ctx hi/lo
    attn_mma_kernel<<<128, 256>>>(qx, qy, qpm, ax, ay, apm, fmask, padm, pex, pey);
    attn_combine_kernel<<<(B * H * Q * DK) / 256, 256>>>(ctx_h, ctx_l);

    // 4. output projection + residual
    gemm_mma<false, true, false><<<dim3(D / 128, (B * Q) / 128), 256, gemm_smem>>>(
        ctx_h, ctx_l, wo_h, wo_l, bo, query_tokens, pres1, nullptr, nullptr,
        B * Q, D, D);

    // 5. LN1 (fused split)
    layernorm_kernel<<<B * Q, 256>>>(pres1, g1, be1, px1, x1_h, x1_l);

    // 6. FFN up + relu (fused split output)
    gemm_mma<true, false, true><<<dim3(DFF / 128, (B * Q) / 128), 256, gemm_smem>>>(
        x1_h, x1_l, w1_h, w1_l, b1, nullptr, nullptr, ff1_h, ff1_l, B * Q, DFF, D);

    // 7. FFN down + residual
    gemm_mma<false, true, false><<<dim3(D / 128, (B * Q) / 128), 256, gemm_smem>>>(
        ff1_h, ff1_l, w2_h, w2_l, b2, px1, pres2, nullptr, nullptr, B * Q, D, DFF);

    // 8. LN2 -> output
    layernorm_kernel<<<B * Q, 256>>>(pres2, g2, be2, out, nullptr, nullptr);
}